// round 6
// baseline (speedup 1.0000x reference)
#include <cuda_runtime.h>
#include <math.h>

#define NB 64
#define NA 8732
#define NA4 2183            // NA/4 exact
#define NA4P 3072           // pad to 3*1024
#define NAP 9216            // pad to 9*1024
#define NG 50
#define NC 21
#define NBX 35              // ceil(NA/256)
#define CAP 3072            // candidate buffer capacity
#define IOU_THR 0.5f
#define VXY 0.1f
#define VWH 0.2f
#define EPS16 9.765625e-4

// ---------------- device scratch ----------------
__device__ float  g_lossneg[NB * NA];
__device__ float  g_psl1[NB * NBX];
__device__ float  g_pce [NB * NBX];
__device__ int    g_pnp [NB * NBX];
__device__ double g_ob_cp[NB];
__device__ double g_ob_cn[NB];
__device__ double g_ob_np[NB];
__device__ double g_ob_sl[NB];
__device__ int    g_ctr;

// ---------------- helpers ----------------
__device__ __forceinline__ double warpRedD(double v) {
    #pragma unroll
    for (int o = 16; o > 0; o >>= 1) v += __shfl_down_sync(0xFFFFFFFFu, v, o);
    return v;
}
__device__ __forceinline__ float warpRedF(float v) {
    #pragma unroll
    for (int o = 16; o > 0; o >>= 1) v += __shfl_down_sync(0xFFFFFFFFu, v, o);
    return v;
}
__device__ __forceinline__ float smoothL1(float d) {
    float ad = fabsf(d);
    return ad < 1.0f ? 0.5f * d * d : ad - 0.5f;
}
__device__ __forceinline__ unsigned ordkey(float f) {
    unsigned u = __float_as_uint(f);
    return u ^ ((u >> 31) ? 0xFFFFFFFFu : 0x80000000u);
}
__device__ __forceinline__ float ordval(unsigned k) {
    unsigned u = (k & 0x80000000u) ? (k ^ 0x80000000u) : ~k;
    return __uint_as_float(u);
}
// warp inclusive suffix sum (sum over lanes >= mine)
__device__ __forceinline__ unsigned warpSufIncl(unsigned v, int lane) {
    #pragma unroll
    for (int d = 1; d < 32; d <<= 1) {
        unsigned t = __shfl_down_sync(0xFFFFFFFFu, v, d);
        if (lane + d < 32) v += t;
    }
    return v;
}
// warp-aggregated append (all lanes must reach the ballot)
__device__ __forceinline__ void ballotAppend(bool take, unsigned u, unsigned* buf,
                                             unsigned* cnt, int lane) {
    unsigned mask = __ballot_sync(0xFFFFFFFFu, take);
    if (take) {
        int leader = __ffs(mask) - 1;
        unsigned base = 0;
        if (lane == leader) base = atomicAdd(cnt, (unsigned)__popc(mask));
        base = __shfl_sync(mask, base, leader);
        unsigned p = base + (unsigned)__popc(mask & ((1u << lane) - 1u));
        if (p < CAP) buf[p] = u;
    }
}

// ---------------- kernel 1: match + box loss + CE ----------------
__global__ __launch_bounds__(256) void k_match(const float* __restrict__ preg,
                        const float* __restrict__ pcls,
                        const float* __restrict__ ancs,
                        const float* __restrict__ gbox,
                        const int*   __restrict__ glab) {
    const int b = blockIdx.y;
    const int a = blockIdx.x * 256 + threadIdx.x;

    __shared__ float4 s_gb[NG];
    __shared__ float  s_ga[NG];
    __shared__ int    s_gl[NG];
    if (threadIdx.x < NG) {
        float4 gb = reinterpret_cast<const float4*>(gbox)[b * NG + threadIdx.x];
        int    gl = glab[b * NG + threadIdx.x];
        float  ag = (gb.z - gb.x) * (gb.w - gb.y);
        if (gl <= 0) { gb = make_float4(0.f, 0.f, 0.f, 0.f); ag = 0.f; }
        s_gb[threadIdx.x] = gb;
        s_ga[threadIdx.x] = ag;
        s_gl[threadIdx.x] = gl;
    }
    __syncthreads();

    float sl1_c = 0.f, ce_c = 0.f;
    int pos_c = 0;

    if (a < NA) {
        float4 anc = reinterpret_cast<const float4*>(ancs)[a];
        float al = anc.x - anc.z * 0.5f;
        float at = anc.y - anc.w * 0.5f;
        float ar = anc.x + anc.z * 0.5f;
        float ab = anc.y + anc.w * 0.5f;
        float area_a = (ar - al) * (ab - at);

        float inb = -1.0f, unb = 1.0f;
        int   bi  = 0;
        #pragma unroll
        for (int g = 0; g < NG; g++) {
            float4 gb = s_gb[g];
            float ltx = fmaxf(gb.x, al), lty = fmaxf(gb.y, at);
            float rbx = fminf(gb.z, ar), rby = fminf(gb.w, ab);
            float w = fmaxf(rbx - ltx, 0.0f), h = fmaxf(rby - lty, 0.0f);
            float inter = w * h;
            float uni = s_ga[g] + area_a - inter;
            if (inter * unb > inb * uni) { inb = inter; unb = uni; bi = g; }
        }
        bool pos = (2.0f * inb >= unb);

        float4 gb = s_gb[bi];
        float gcx = (gb.x + gb.z) * 0.5f, gcy = (gb.y + gb.w) * 0.5f;
        float gw = gb.z - gb.x, gh = gb.w - gb.y;
        float tx = (gcx - anc.x) / (anc.z * VXY);
        float ty = (gcy - anc.y) / (anc.w * VXY);
        float tw = __logf(fmaxf(gw, 1e-6f) / anc.z) * (1.0f / VWH);
        float th = __logf(fmaxf(gh, 1e-6f) / anc.w) * (1.0f / VWH);
        float d0 = preg[(b * 4 + 0) * NA + a] - tx;
        float d1 = preg[(b * 4 + 1) * NA + a] - ty;
        float d2 = preg[(b * 4 + 2) * NA + a] - tw;
        float d3 = preg[(b * 4 + 3) * NA + a] - th;
        float sl1 = smoothL1(d0) + smoothL1(d1) + smoothL1(d2) + smoothL1(d3);

        const float* pc = pcls + (size_t)b * NC * NA + a;
        float m = -1e30f;
        float xs[NC];
        #pragma unroll
        for (int c = 0; c < NC; c++) {
            xs[c] = pc[c * NA];
            m = fmaxf(m, xs[c]);
        }
        float s = 0.0f;
        #pragma unroll
        for (int c = 0; c < NC; c++) s += __expf(xs[c] - m);
        float lse = m + __logf(s);
        int lab = pos ? s_gl[bi] : 0;
        float xlab = pc[lab * NA];
        float ce = lse - xlab;

        g_lossneg[b * NA + a] = pos ? -1.0f : ce;
        if (pos) { pos_c = 1; ce_c = ce; sl1_c = sl1; }
    }

    sl1_c = warpRedF(sl1_c);
    ce_c  = warpRedF(ce_c);
    float posf = warpRedF((float)pos_c);
    __shared__ float sh0[8], sh1[8], sh2[8];
    int wid = threadIdx.x >> 5, lid = threadIdx.x & 31;
    if (lid == 0) { sh0[wid] = sl1_c; sh1[wid] = ce_c; sh2[wid] = posf; }
    __syncthreads();
    if (wid == 0) {
        float v0 = (lid < 8) ? sh0[lid] : 0.f;
        float v1 = (lid < 8) ? sh1[lid] : 0.f;
        float v2 = (lid < 8) ? sh2[lid] : 0.f;
        v0 = warpRedF(v0); v1 = warpRedF(v1); v2 = warpRedF(v2);
        if (lid == 0) {
            int p = b * NBX + blockIdx.x;
            g_psl1[p] = v0;
            g_pce [p] = v1;
            g_pnp [p] = (int)(v2 + 0.5f);
        }
    }
}

// ---------------- select-bin over s_hist[nbins], nbins in {1024,2048} ----------------
// writes *s_bin and *s_remS; all-threads collective.
__device__ __forceinline__ void selectBin(unsigned* hist, int nbins, unsigned rem,
        unsigned* s_wsum, unsigned* s_wsum2, unsigned* s_bin, int* s_remS,
        int tid, int lane, int wid) {
    int bpt = nbins >> 10;               // 1 or 2 bins per thread
    int base = tid * bpt;
    unsigned h0 = hist[base];
    unsigned h1 = (bpt == 2) ? hist[base + 1] : 0u;
    unsigned lt = h0 + h1;
    unsigned v = warpSufIncl(lt, lane);  // warp suffix incl
    if (lane == 0) s_wsum[wid] = v;      // warp total
    __syncthreads();
    if (tid < 32) {
        unsigned t = s_wsum[tid];
        s_wsum2[tid] = warpSufIncl(t, tid);
    }
    __syncthreads();
    unsigned wexcl = (wid < 31) ? s_wsum2[wid + 1] : 0u;
    unsigned suf0 = v + wexcl;           // block suffix incl my first bin
    unsigned nxt0 = suf0 - h0;
    if (nxt0 < rem && rem <= suf0) { *s_bin = (unsigned)base; *s_remS = (int)(rem - nxt0); }
    if (bpt == 2) {
        unsigned suf1 = nxt0, nxt1 = suf1 - h1;
        if (nxt1 < rem && rem <= suf1) { *s_bin = (unsigned)(base + 1); *s_remS = (int)(rem - nxt1); }
    }
    __syncthreads();
}

// ---------------- kernel 2: compacting radix top-K + final combine ----------------
__global__ __launch_bounds__(1024) void k_select(float* __restrict__ out) {
    const int b = blockIdx.x;
    const int tid = threadIdx.x;
    const int lane = tid & 31;
    const int wid = tid >> 5;

    __shared__ unsigned s_hist[2048];
    __shared__ unsigned s_cand0[CAP];
    __shared__ unsigned s_cand1[CAP];
    __shared__ unsigned s_wsum[32], s_wsum2[32];
    __shared__ unsigned s_bin, s_cnt;
    __shared__ int s_remS;
    __shared__ double s_np, s_ce, s_sl;
    __shared__ int s_ticket;
    __shared__ double sd[32];

    // zero hist; warp 8 reduces per-block partials concurrently
    for (int i = tid; i < 2048; i += 1024) s_hist[i] = 0;
    if (tid >= 256 && tid < 288) {
        int t = tid - 256;
        double np = 0.0, ce = 0.0, sl = 0.0;
        for (int i = t; i < NBX; i += 32) {
            int p = b * NBX + i;
            np += (double)g_pnp[p];
            ce += (double)g_pce[p];
            sl += (double)g_psl1[p];
        }
        np = warpRedD(np); ce = warpRedD(ce); sl = warpRedD(sl);
        if (t == 0) { s_np = np; s_ce = ce; s_sl = sl; }
    }
    if (tid == 0) s_cnt = 0;
    __syncthreads();

    int npos = (int)(s_np + 0.5);
    int numneg = NA - npos;
    int K = (npos > 0) ? min(3 * npos, numneg) : (numneg > 0 ? 1 : 0);

    const float*  basef = &g_lossneg[b * NA];
    const float4* base4 = reinterpret_cast<const float4*>(basef);

    double dsum = 0.0;       // accumulated sum of values strictly above pivot
    double negsum = 0.0;

    if (K > 0) {
        // ---- round 1: top 11 bits ----
        for (int i = tid; i < NA4; i += 1024) {
            float4 v = base4[i];
            atomicAdd(&s_hist[ordkey(v.x) >> 21], 1u);
            atomicAdd(&s_hist[ordkey(v.y) >> 21], 1u);
            atomicAdd(&s_hist[ordkey(v.z) >> 21], 1u);
            atomicAdd(&s_hist[ordkey(v.w) >> 21], 1u);
        }
        __syncthreads();
        selectBin(s_hist, 2048, (unsigned)K, s_wsum, s_wsum2, &s_bin, &s_remS, tid, lane, wid);
        unsigned b1 = s_bin;
        unsigned rem = (unsigned)s_remS;
        unsigned pval = b1 << 21, pmask = 0xFFE00000u;

        // sum above + compact bin members
        for (int i = tid; i < NA4P; i += 1024) {
            bool vld = (i < NA4);
            float4 v = make_float4(0.f, 0.f, 0.f, 0.f);
            if (vld) v = base4[i];
            unsigned u0 = ordkey(v.x), u1 = ordkey(v.y), u2 = ordkey(v.z), u3 = ordkey(v.w);
            if (vld) {
                if ((u0 >> 21) > b1) dsum += (double)v.x;
                if ((u1 >> 21) > b1) dsum += (double)v.y;
                if ((u2 >> 21) > b1) dsum += (double)v.z;
                if ((u3 >> 21) > b1) dsum += (double)v.w;
            }
            ballotAppend(vld && (u0 >> 21) == b1, u0, s_cand0, &s_cnt, lane);
            ballotAppend(vld && (u1 >> 21) == b1, u1, s_cand0, &s_cnt, lane);
            ballotAppend(vld && (u2 >> 21) == b1, u2, s_cand0, &s_cnt, lane);
            ballotAppend(vld && (u3 >> 21) == b1, u3, s_cand0, &s_cnt, lane);
        }
        __syncthreads();
        unsigned M1 = s_cnt;
        bool mode1 = (M1 <= CAP);      // true: use cand buffer

        // ---- round 2: bits [10,21) ----
        for (int i = tid; i < 2048; i += 1024) s_hist[i] = 0;
        if (tid == 0) s_cnt = 0;
        __syncthreads();
        if (mode1) {
            for (int i = tid; i < (int)M1; i += 1024)
                atomicAdd(&s_hist[(s_cand0[i] >> 10) & 2047u], 1u);
        } else {
            for (int i = tid; i < NA; i += 1024) {
                unsigned u = ordkey(basef[i]);
                if ((u & pmask) == pval) atomicAdd(&s_hist[(u >> 10) & 2047u], 1u);
            }
        }
        __syncthreads();
        selectBin(s_hist, 2048, rem, s_wsum, s_wsum2, &s_bin, &s_remS, tid, lane, wid);
        unsigned b2 = s_bin;
        rem = (unsigned)s_remS;

        if (mode1) {
            int Mp = (int)((M1 + 1023u) & ~1023u);
            for (int i = tid; i < Mp; i += 1024) {
                bool vld = (i < (int)M1);
                unsigned u = vld ? s_cand0[i] : 0u;
                unsigned bk = (u >> 10) & 2047u;
                if (vld && bk > b2) dsum += (double)ordval(u);
                ballotAppend(vld && bk == b2, u, s_cand1, &s_cnt, lane);
            }
        } else {
            for (int i = tid; i < NAP; i += 1024) {
                bool vld = false; unsigned u = 0;
                if (i < NA) { u = ordkey(basef[i]); vld = ((u & pmask) == pval); }
                unsigned bk = (u >> 10) & 2047u;
                if (vld && bk > b2) dsum += (double)ordval(u);
                ballotAppend(vld && bk == b2, u, s_cand1, &s_cnt, lane);
            }
        }
        __syncthreads();
        unsigned M2 = s_cnt;
        bool mode2 = (M2 <= CAP);
        pval |= b2 << 10; pmask |= 0x001FFC00u;

        // ---- round 3: bits [0,10) ----
        for (int i = tid; i < 1024; i += 1024) s_hist[i] = 0;
        __syncthreads();
        if (mode2) {
            for (int i = tid; i < (int)M2; i += 1024)
                atomicAdd(&s_hist[s_cand1[i] & 1023u], 1u);
        } else {
            for (int i = tid; i < NA; i += 1024) {
                unsigned u = ordkey(basef[i]);
                if ((u & pmask) == pval) atomicAdd(&s_hist[u & 1023u], 1u);
            }
        }
        __syncthreads();
        selectBin(s_hist, 1024, rem, s_wsum, s_wsum2, &s_bin, &s_remS, tid, lane, wid);
        unsigned b3 = s_bin;
        rem = (unsigned)s_remS;

        if (mode2) {
            for (int i = tid; i < (int)M2; i += 1024) {
                unsigned u = s_cand1[i];
                if ((u & 1023u) > b3) dsum += (double)ordval(u);
            }
        } else {
            for (int i = tid; i < NA; i += 1024) {
                unsigned u = ordkey(basef[i]);
                if ((u & pmask) == pval && (u & 1023u) > b3) dsum += (double)ordval(u);
            }
        }

        unsigned pivot = pval | b3;
        float pv = ordval(pivot);

        double s = warpRedD(dsum);
        if (lane == 0) sd[wid] = s;
        __syncthreads();
        if (tid < 32) {
            double t = sd[tid];
            t = warpRedD(t);
            if (tid == 0) sd[0] = t + (double)rem * (double)pv;
        }
        __syncthreads();
        negsum = sd[0];
    }

    // publish per-batch results; last block combines
    if (tid == 0) {
        double nums = fmax(s_np, (double)EPS16);
        g_ob_cp[b] = s_ce / nums;
        g_ob_cn[b] = negsum / nums;
        g_ob_np[b] = s_np;
        g_ob_sl[b] = s_sl;
        __threadfence();
        s_ticket = atomicAdd(&g_ctr, 1);
    }
    __syncthreads();

    if (s_ticket == NB - 1) {
        double cp = 0.0, cn = 0.0, np = 0.0, sl = 0.0;
        if (tid < NB) {
            cp = g_ob_cp[tid]; cn = g_ob_cn[tid];
            np = g_ob_np[tid]; sl = g_ob_sl[tid];
        }
        cp = warpRedD(cp); cn = warpRedD(cn); np = warpRedD(np); sl = warpRedD(sl);
        __shared__ double f0[2], f1[2], f2[2], f3[2];
        if (lane == 0 && tid < NB) {
            f0[wid] = cp; f1[wid] = cn; f2[wid] = np; f3[wid] = sl;
        }
        __syncthreads();
        if (tid == 0) {
            double CP = f0[0] + f0[1];
            double CN = f1[0] + f1[1];
            double NP = f2[0] + f2[1];
            double SL = f3[0] + f3[1];
            double lbox = SL / fmax(NP, 1.0);
            out[0] = (float)(lbox + CP / (double)NB + CN / (double)NB);
            g_ctr = 0;
        }
    }
}

// ---------------- launch ----------------
extern "C" void kernel_launch(void* const* d_in, const int* in_sizes, int n_in,
                              void* d_out, int out_size) {
    const float* preg = (const float*)d_in[0];
    const float* pcls = (const float*)d_in[1];
    const float* ancs = (const float*)d_in[2];
    const float* gbox = (const float*)d_in[3];
    const int*   glab = (const int*)d_in[4];
    float* out = (float*)d_out;

    dim3 grid(NBX, NB);
    k_match<<<grid, 256>>>(preg, pcls, ancs, gbox, glab);
    k_select<<<NB, 1024>>>(out);
}